// round 14
// baseline (speedup 1.0000x reference)
#include <cuda_runtime.h>
#include <cuda_fp16.h>
#include <math.h>
#include <stdint.h>

// Problem dims
#define Bq 4
#define Sq 1024
#define Dq 1024
#define Hq 16
#define HSq 64
#define FFq 4096
#define Lq 6
#define Mq (Bq*Sq)      // 4096 token rows
#define QKVN 3072       // merged QKV output width

// ---------------- scratch (static device memory; no allocations) ----------
__device__ float  g_x  [Mq*Dq];                      // fp32 residual stream
__device__ __half g_t1h[Mq*Dq];
__device__ __half g_xh [Mq*Dq];
__device__ __half g_qkv[(size_t)Mq*QKVN];            // merged q|k|v rows
__device__ __half g_ctxh[Mq*Dq];
__device__ __half g_ffh[(size_t)Mq*FFq];
__device__ __half g_wch[(size_t)Lq*(4*Dq*Dq + 2*Dq*FFq)];   // weights half
__device__ float  g_bqkv[Lq*QKVN];                   // concat qkv bias

// ---------------- helpers ---------------------------------------------------
__device__ __forceinline__ void mma16(float* d, const unsigned* a,
                                      unsigned b0, unsigned b1){
    asm volatile(
        "mma.sync.aligned.m16n8k16.row.col.f32.f16.f16.f32 "
        "{%0,%1,%2,%3},{%4,%5,%6,%7},{%8,%9},{%0,%1,%2,%3};\n"
        : "+f"(d[0]), "+f"(d[1]), "+f"(d[2]), "+f"(d[3])
        : "r"(a[0]), "r"(a[1]), "r"(a[2]), "r"(a[3]), "r"(b0), "r"(b1));
}

__device__ __forceinline__ void ldsm4(unsigned* r, unsigned addr){
    asm volatile("ldmatrix.sync.aligned.m8n8.x4.shared.b16 {%0,%1,%2,%3}, [%4];"
        : "=r"(r[0]), "=r"(r[1]), "=r"(r[2]), "=r"(r[3]) : "r"(addr));
}
__device__ __forceinline__ void ldsm4t(unsigned* r, unsigned addr){
    asm volatile("ldmatrix.sync.aligned.m8n8.x4.trans.shared.b16 {%0,%1,%2,%3}, [%4];"
        : "=r"(r[0]), "=r"(r[1]), "=r"(r[2]), "=r"(r[3]) : "r"(addr));
}

__device__ __forceinline__ void cp16(unsigned dst, const void* src){
    asm volatile("cp.async.cg.shared.global [%0], [%1], 16;\n" :: "r"(dst), "l"(src));
}
__device__ __forceinline__ void cp_commit(){ asm volatile("cp.async.commit_group;\n"); }
__device__ __forceinline__ unsigned smem_u32(const void* p){
    return (unsigned)__cvta_generic_to_shared(p);
}
__device__ __forceinline__ float ex2(float x){
    float r; asm("ex2.approx.ftz.f32 %0, %1;" : "=f"(r) : "f"(x)); return r;
}
__device__ __forceinline__ uint4 pack8(float4 a, float4 b){
    half2 h0 = __floats2half2_rn(a.x, a.y);
    half2 h1 = __floats2half2_rn(a.z, a.w);
    half2 h2 = __floats2half2_rn(b.x, b.y);
    half2 h3 = __floats2half2_rn(b.z, b.w);
    uint4 o;
    o.x = *(unsigned*)&h0; o.y = *(unsigned*)&h1;
    o.z = *(unsigned*)&h2; o.w = *(unsigned*)&h3;
    return o;
}

// ================== fused flash attention (no-max softmax, occ 2) ==========
#define QSTR 72
#define VSTR 72
#define FA_SMEM (128*QSTR*2 + 2*128*QSTR*2 + 2*128*VSTR*2 + 1024*4)

__global__ __launch_bounds__(256, 2)
void flash_attn(const __half* __restrict__ qh,
                const __half* __restrict__ kh,
                const __half* __restrict__ vh,
                const int*    __restrict__ mask,
                __half* __restrict__ ctxh,
                int ldq)
{
    extern __shared__ __align__(16) char fsm[];
    __half* Qs = (__half*)fsm;
    __half* Ks = Qs + 128 * QSTR;
    __half* Vs = Ks + 2 * 128 * QSTR;
    float*  ms = (float*)(Vs + 2 * 128 * VSTR);

    const int tid  = threadIdx.x;
    const int lane = tid & 31;
    const int w    = tid >> 5;
    const int g    = lane >> 2;
    const int t4   = lane & 3;
    const int grp  = lane >> 3;
    const int l8   = lane & 7;
    const int ofs1 = (grp & 1) * 8;
    const int ofs2 = (grp >> 1) * 8;
    const int bh = blockIdx.y;
    const int b  = bh >> 4, h = bh & 15;
    const int q0 = blockIdx.x * 128;
    const float SC = 0.125f * 1.44269504f;

    const unsigned qs = smem_u32(Qs), ks_ = smem_u32(Ks), vs_ = smem_u32(Vs);

    const size_t qbase = ((size_t)b * Sq + q0) * ldq + (size_t)h * HSq;
    #pragma unroll
    for (int c = 0; c < 4; c++) {
        int i = tid + c * 256, row = i >> 3, kc = (i & 7) * 8;
        cp16(qs + (unsigned)(row * QSTR + kc) * 2u,
             qh + qbase + (size_t)row * ldq + kc);
    }
    cp_commit();
    #pragma unroll
    for (int c = 0; c < 4; c++) {
        int i = tid + c * 256;
        ms[i] = mask[b * Sq + i] ? 0.f : -1.0e30f;
    }

    auto load_kv = [&](int kb, int st){
        const int kv0 = kb * 128;
        const size_t kbase = ((size_t)b * Sq + kv0) * ldq + (size_t)h * HSq;
        const unsigned kdst = ks_ + (unsigned)(st * 128 * QSTR) * 2u;
        const unsigned vdst = vs_ + (unsigned)(st * 128 * VSTR) * 2u;
        #pragma unroll
        for (int c = 0; c < 4; c++) {
            int i = tid + c * 256, row = i >> 3, kc = (i & 7) * 8;
            cp16(kdst + (unsigned)(row * QSTR + kc) * 2u,
                 kh + kbase + (size_t)row * ldq + kc);
        }
        #pragma unroll
        for (int c = 0; c < 4; c++) {
            int i = tid + c * 256, row = i >> 3, kc = (i & 7) * 8;
            cp16(vdst + (unsigned)(row * VSTR + kc) * 2u,
                 vh + kbase + (size_t)row * ldq + kc);
        }
        cp_commit();
    };

    load_kv(0, 0);

    asm volatile("cp.async.wait_group 1;\n");
    __syncthreads();

    unsigned qa[4][4];
    {
        const int rq = w * 16;
        #pragma unroll
        for (int ks = 0; ks < 4; ks++) {
            qa[ks][0] = *(const unsigned*)&Qs[(rq + g    ) * QSTR + ks*16 + 2*t4    ];
            qa[ks][1] = *(const unsigned*)&Qs[(rq + g + 8) * QSTR + ks*16 + 2*t4    ];
            qa[ks][2] = *(const unsigned*)&Qs[(rq + g    ) * QSTR + ks*16 + 2*t4 + 8];
            qa[ks][3] = *(const unsigned*)&Qs[(rq + g + 8) * QSTR + ks*16 + 2*t4 + 8];
        }
    }

    float O[8][4];
    #pragma unroll
    for (int t = 0; t < 8; t++)
        #pragma unroll
        for (int r = 0; r < 4; r++) O[t][r] = 0.f;
    float l0 = 0.f, l1 = 0.f;

    for (int kb = 0; kb < 8; kb++) {
        const int st = kb & 1;
        if (kb + 1 < 8) {
            load_kv(kb + 1, st ^ 1);
            asm volatile("cp.async.wait_group 1;\n");
        } else {
            asm volatile("cp.async.wait_group 0;\n");
        }
        __syncthreads();

        const unsigned K_ = ks_ + (unsigned)(st * 128 * QSTR) * 2u;
        const unsigned V_ = vs_ + (unsigned)(st * 128 * VSTR) * 2u;

        #pragma unroll
        for (int hf = 0; hf < 2; hf++) {
            float c[8][4];
            #pragma unroll
            for (int t = 0; t < 8; t++)
                #pragma unroll
                for (int r = 0; r < 4; r++) c[t][r] = 0.f;
            #pragma unroll
            for (int t2 = 0; t2 < 4; t2++) {
                const int t2g = hf * 4 + t2;
                unsigned kf[4][4];
                #pragma unroll
                for (int ks = 0; ks < 4; ks++)
                    ldsm4(kf[ks], K_ + (unsigned)((t2g*16 + ofs1 + l8) * QSTR
                                                  + ks*16 + ofs2) * 2u);
                #pragma unroll
                for (int ks = 0; ks < 4; ks++) {
                    mma16(c[2*t2    ], qa[ks], kf[ks][0], kf[ks][2]);
                    mma16(c[2*t2 + 1], qa[ks], kf[ks][1], kf[ks][3]);
                }
            }

            unsigned pa[4][4];
            #pragma unroll
            for (int t = 0; t < 8; t++) {
                const int tg = hf * 8 + t;
                float2 mb = *(const float2*)&ms[kb*128 + tg*8 + 2*t4];
                float p0 = ex2(c[t][0] * SC + mb.x);
                float p1 = ex2(c[t][1] * SC + mb.y);
                float p2 = ex2(c[t][2] * SC + mb.x);
                float p3 = ex2(c[t][3] * SC + mb.y);
                l0 += p0 + p1;  l1 += p2 + p3;
                half2 h01 = __floats2half2_rn(p0, p1);
                half2 h23 = __floats2half2_rn(p2, p3);
                const int ks = t >> 1, sub = (t & 1) * 2;
                pa[ks][sub    ] = *(unsigned*)&h01;
                pa[ks][sub + 1] = *(unsigned*)&h23;
            }

            #pragma unroll
            for (int ks = 0; ks < 4; ks++) {
                const int ksg = hf * 4 + ks;
                unsigned vf[4][4];
                #pragma unroll
                for (int h2 = 0; h2 < 4; h2++)
                    ldsm4t(vf[h2], V_ + (unsigned)((ksg*16 + ofs1 + l8) * VSTR
                                                   + h2*16 + ofs2) * 2u);
                #pragma unroll
                for (int h2 = 0; h2 < 4; h2++) {
                    mma16(O[2*h2    ], pa[ks], vf[h2][0], vf[h2][1]);
                    mma16(O[2*h2 + 1], pa[ks], vf[h2][2], vf[h2][3]);
                }
            }
        }
        __syncthreads();
    }

    l0 += __shfl_xor_sync(0xffffffffu, l0, 1);
    l0 += __shfl_xor_sync(0xffffffffu, l0, 2);
    l1 += __shfl_xor_sync(0xffffffffu, l1, 1);
    l1 += __shfl_xor_sync(0xffffffffu, l1, 2);
    const float r0 = 1.f / l0, r1 = 1.f / l1;
    const int row0 = q0 + w * 16 + g;
    #pragma unroll
    for (int t = 0; t < 8; t++) {
        half2 o01 = __floats2half2_rn(O[t][0] * r0, O[t][1] * r0);
        half2 o23 = __floats2half2_rn(O[t][2] * r1, O[t][3] * r1);
        size_t base = ((size_t)b * Sq + row0) * Dq + h * HSq + t*8 + 2*t4;
        *(half2*)&ctxh[base]          = o01;
        *(half2*)&ctxh[base + 8 * Dq] = o23;
    }
}

// ================== fp16 GEMM: A[M,K] @ B[K,N], BK=64, 3-stage pipeline ====
#define BM 128
#define BKh 64
#define ASTR 72
#define NSTRIDE 136
#define GH_A_STG (BM * ASTR * 2)
#define GH_B_STG (BKh * NSTRIDE * 2)
#define GH_STG   (GH_A_STG + GH_B_STG)
#define GH_SMEM  (3 * GH_STG)

template<int BNt>
__global__ __launch_bounds__(256, 2)
void gemm_h(const __half* __restrict__ A, int lda,
            const __half* __restrict__ Bm, int ldb,
            __half* __restrict__ Ch, int ldc,
            int M, int N, int K,
            const float* __restrict__ bias, int relu)
{
    constexpr int NI   = BNt / 16;
    constexpr int NP   = NI / 2;
    constexpr int A_CP = (BM  * BKh) / (8 * 256);
    constexpr int B_CP = (BKh * BNt) / (8 * 256);

    extern __shared__ __align__(16) char gsm[];

    const int m0 = blockIdx.y * BM;
    const int n0 = blockIdx.x * BNt;
    const int tid  = threadIdx.x;
    const int lane = tid & 31;
    const int w    = tid >> 5;
    const int wm   = (w >> 1) * 32;
    const int wn   = (w & 1) * (BNt / 2);
    const int g    = lane >> 2;
    const int t4   = lane & 3;
    const int grp  = lane >> 3;
    const int l8   = lane & 7;
    const int ofs1 = (grp & 1) * 8;
    const int ofs2 = (grp >> 1) * 8;

    const unsigned sb = smem_u32(gsm);
    unsigned as_base[3], bs_base[3];
    #pragma unroll
    for (int s = 0; s < 3; s++) {
        as_base[s] = sb + s * GH_STG;
        bs_base[s] = sb + s * GH_STG + GH_A_STG;
    }

    const unsigned a_off = (unsigned)((ofs1 + l8) * ASTR + ofs2);

    float acc[2][NI][4];
    #pragma unroll
    for (int mi = 0; mi < 2; mi++)
        #pragma unroll
        for (int ni = 0; ni < NI; ni++)
            #pragma unroll
            for (int r = 0; r < 4; r++) acc[mi][ni][r] = 0.f;

    const int niter = K / BKh;

    auto load_stage = [&](int it, int buf) {
        const long long k0 = (long long)it * BKh;
        #pragma unroll
        for (int c = 0; c < A_CP; c++) {
            int q = tid + c * 256, row = q >> 3, kc = (q & 7) * 8;
            cp16(as_base[buf] + (unsigned)(row * ASTR + kc) * 2u,
                 A + (size_t)(m0 + row) * lda + k0 + kc);
        }
        #pragma unroll
        for (int c = 0; c < B_CP; c++) {
            int q = tid + c * 256, row = q >> 4, cc = (q & 15) * 8;
            cp16(bs_base[buf] + (unsigned)(row * NSTRIDE + cc) * 2u,
                 Bm + (size_t)(k0 + row) * ldb + n0 + cc);
        }
        cp_commit();
    };

    load_stage(0, 0);
    if (niter > 1) load_stage(1, 1);

    for (int it = 0; it < niter; it++) {
        if (it + 2 < niter)
            load_stage(it + 2, (it + 2) % 3);
        const int rem = niter - 1 - it;
        if      (rem >= 2) asm volatile("cp.async.wait_group 2;\n");
        else if (rem == 1) asm volatile("cp.async.wait_group 1;\n");
        else               asm volatile("cp.async.wait_group 0;\n");
        __syncthreads();

        const int buf = it % 3;
        const unsigned as_ = as_base[buf];
        const unsigned bs_ = bs_base[buf];

        #pragma unroll
        for (int kk = 0; kk < BKh; kk += 16) {
            unsigned a[2][4], bf[NP][4];
            #pragma unroll
            for (int mi = 0; mi < 2; mi++)
                ldsm4(a[mi], as_ + ((unsigned)((wm + mi*16) * ASTR + kk) + a_off) * 2u);
            #pragma unroll
            for (int np = 0; np < NP; np++)
                ldsm4t(bf[np], bs_ + (unsigned)((kk + ofs1 + l8) * NSTRIDE
                                                + wn + np*16 + ofs2) * 2u);
            #pragma unroll
            for (int mi = 0; mi < 2; mi++)
                #pragma unroll
                for (int np = 0; np < NP; np++) {
                    mma16(acc[mi][np*2    ], a[mi], bf[np][0], bf[np][1]);
                    mma16(acc[mi][np*2 + 1], a[mi], bf[np][2], bf[np][3]);
                }
        }
        __syncthreads();
    }

    #pragma unroll
    for (int mi = 0; mi < 2; mi++) {
        int r0 = m0 + wm + mi * 16 + g;
        #pragma unroll
        for (int ni = 0; ni < NI; ni++) {
            int c = n0 + wn + ni * 8 + t4 * 2;
            float b0 = bias ? bias[c]     : 0.f;
            float b1 = bias ? bias[c + 1] : 0.f;
            float v00 = acc[mi][ni][0] + b0;
            float v01 = acc[mi][ni][1] + b1;
            float v10 = acc[mi][ni][2] + b0;
            float v11 = acc[mi][ni][3] + b1;
            if (relu) {
                v00 = fmaxf(v00, 0.f); v01 = fmaxf(v01, 0.f);
                v10 = fmaxf(v10, 0.f); v11 = fmaxf(v11, 0.f);
            }
            *(half2*)&Ch[(size_t)r0 * ldc + c]       = __floats2half2_rn(v00, v01);
            *(half2*)&Ch[(size_t)(r0 + 8) * ldc + c] = __floats2half2_rn(v10, v11);
        }
    }
}

// ---------------- fp32 -> fp16 weight convert, contiguous (4x unrolled) ----
__global__ void wconv(const float4* __restrict__ src, uint4* __restrict__ dst,
                      int n8)
{
    const int S = gridDim.x * blockDim.x;
    int i = blockIdx.x * blockDim.x + threadIdx.x;
    float4 a0 = src[(size_t)i*2],           b0 = src[(size_t)i*2 + 1];
    float4 a1 = src[(size_t)(i+S)*2],       b1 = src[(size_t)(i+S)*2 + 1];
    float4 a2 = src[(size_t)(i+2*S)*2],     b2 = src[(size_t)(i+2*S)*2 + 1];
    float4 a3 = src[(size_t)(i+3*S)*2],     b3 = src[(size_t)(i+3*S)*2 + 1];
    dst[i      ] = pack8(a0, b0);
    dst[i +   S] = pack8(a1, b1);
    dst[i + 2*S] = pack8(a2, b2);
    dst[i + 3*S] = pack8(a3, b3);
}

// ---------------- fp32 -> fp16 weight convert into QKV-concat layout -------
__global__ void wconvs(const float4* __restrict__ src, uint4* __restrict__ dst,
                       int n8)
{
    const int S = gridDim.x * blockDim.x;
    int i = blockIdx.x * blockDim.x + threadIdx.x;
    #pragma unroll
    for (int u = 0; u < 4; u++) {
        int j = i + u * S;
        float4 a = src[(size_t)j*2], b = src[(size_t)j*2 + 1];
        dst[(size_t)(j >> 7) * 384 + (j & 127)] = pack8(a, b);
    }
}

// ---------------- concat qkv biases -----------------------------------------
__global__ void bias_cat(const float* __restrict__ bq,
                         const float* __restrict__ bk,
                         const float* __restrict__ bv,
                         float* __restrict__ o)
{
    int idx = blockIdx.x * 256 + threadIdx.x;        // Lq*3072 total
    int l = idx / QKVN, j = idx % QKVN;
    const float* s = (j < 1024) ? bq : (j < 2048) ? bk : bv;
    o[idx] = s[l * 1024 + (j & 1023)];
}

// ---------------- embedding + positional encoding (fp32 + half out) --------
__global__ void embed_pe(const int* __restrict__ src,
                         const float* __restrict__ emb,
                         float* __restrict__ x,
                         __half* __restrict__ xh)
{
    size_t i = (size_t)blockIdx.x * blockDim.x + threadIdx.x;
    int d  = (int)(i & (Dq - 1));
    size_t bs = i >> 10;
    int s  = (int)(bs & (Sq - 1));
    int tok = src[bs];
    float ex  = (float)(d & ~1) / (float)Dq;
    float inv = expf(-9.210340371976184f * ex);
    float ang = (float)s * inv;
    float pe  = (d & 1) ? cosf(ang) : sinf(ang);
    float v = emb[(size_t)tok * Dq + d] + pe;
    x[i]  = v;
    xh[i] = __float2half(v);
}

// ---------------- fused residual-add + LayerNorm (vectorized) --------------
__global__ void add_ln(const __half* __restrict__ a,
                       const float* __restrict__ xres,
                       const float* __restrict__ sc,
                       const float* __restrict__ sh,
                       float* __restrict__ out_f,
                       __half* __restrict__ out_h)
{
    __shared__ float r1[8], r2[8];
    const int row = blockIdx.x;
    const int tid = threadIdx.x;
    const int c0  = tid * 4;
    const __half* ar = a    + (size_t)row * Dq;
    const float*  xr = xres + (size_t)row * Dq;

    uint2 av = *(const uint2*)&ar[c0];
    half2 a01 = *(half2*)&av.x, a23 = *(half2*)&av.y;
    float4 xv = *(const float4*)&xr[c0];
    float v0 = __low2float(a01)  + xv.x;
    float v1 = __high2float(a01) + xv.y;
    float v2 = __low2float(a23)  + xv.z;
    float v3 = __high2float(a23) + xv.w;

    float sum = v0 + v1 + v2 + v3;
    float sq  = v0*v0 + v1*v1 + v2*v2 + v3*v3;
    #pragma unroll
    for (int o = 16; o; o >>= 1) {
        sum += __shfl_xor_sync(0xffffffffu, sum, o);
        sq  += __shfl_xor_sync(0xffffffffu, sq,  o);
    }
    if ((tid & 31) == 0) { r1[tid >> 5] = sum; r2[tid >> 5] = sq; }
    __syncthreads();
    sum = 0.f; sq = 0.f;
    #pragma unroll
    for (int i = 0; i < 8; i++) { sum += r1[i]; sq += r2[i]; }
    float mu  = sum * (1.f / Dq);
    float var = sq * (1.f / Dq) - mu * mu;
    float inv = rsqrtf(var + 1e-5f);

    float4 sv = *(const float4*)&sc[c0];
    float4 hv = *(const float4*)&sh[c0];
    float o0 = (v0 - mu) * inv * sv.x + hv.x;
    float o1 = (v1 - mu) * inv * sv.y + hv.y;
    float o2 = (v2 - mu) * inv * sv.z + hv.z;
    float o3 = (v3 - mu) * inv * sv.w + hv.w;

    *(float4*)&out_f[(size_t)row * Dq + c0] = make_float4(o0, o1, o2, o3);
    if (out_h) {
        half2 p0 = __floats2half2_rn(o0, o1);
        half2 p1 = __floats2half2_rn(o2, o3);
        uint2 pv; pv.x = *(unsigned*)&p0; pv.y = *(unsigned*)&p1;
        *(uint2*)&out_h[(size_t)row * Dq + c0] = pv;
    }
}

// ---------------- host-side GEMM launcher -----------------------------------
static void gemm(const __half* A, int lda, const __half* Bm, int ldb,
                 __half* Ch, int ldc, int M, int N, int K,
                 const float* bias, int relu)
{
    dim3 grid(N / 128, M / BM, 1);
    gemm_h<128><<<grid, 256, GH_SMEM>>>(A, lda, Bm, ldb, Ch, ldc, M, N, K,
                                        bias, relu);
}

// ---------------- entry point ------------------------------------------------
extern "C" void kernel_launch(void* const* d_in, const int* in_sizes, int n_in,
                              void* d_out, int out_size)
{
    const int*   src  = (const int*)  d_in[0];
    const int*   mask = (const int*)  d_in[1];
    const float* emb  = (const float*)d_in[2];
    const float* Wqp  = (const float*)d_in[3];
    const float* bqp  = (const float*)d_in[4];
    const float* Wkp  = (const float*)d_in[5];
    const float* bkp  = (const float*)d_in[6];
    const float* Wvp  = (const float*)d_in[7];
    const float* bvp  = (const float*)d_in[8];
    const float* Wop  = (const float*)d_in[9];
    const float* bop  = (const float*)d_in[10];
    const float* l1s  = (const float*)d_in[11];
    const float* l1b  = (const float*)d_in[12];
    const float* W1p  = (const float*)d_in[13];
    const float* b1p  = (const float*)d_in[14];
    const float* W2p  = (const float*)d_in[15];
    const float* b2p  = (const float*)d_in[16];
    const float* l2s  = (const float*)d_in[17];
    const float* l2b  = (const float*)d_in[18];
    float* out = (float*)d_out;

    static int init_done = 0;
    static cudaStream_t side = nullptr;
    static cudaEvent_t ev0 = nullptr, evA = nullptr, evB = nullptr;
    if (!init_done) {
        cudaFuncSetAttribute(flash_attn,
                             cudaFuncAttributeMaxDynamicSharedMemorySize, FA_SMEM);
        cudaFuncSetAttribute(gemm_h<128>,
                             cudaFuncAttributeMaxDynamicSharedMemorySize, GH_SMEM);
        cudaStreamCreateWithFlags(&side, cudaStreamNonBlocking);
        cudaEventCreateWithFlags(&ev0, cudaEventDisableTiming);
        cudaEventCreateWithFlags(&evA, cudaEventDisableTiming);
        cudaEventCreateWithFlags(&evB, cudaEventDisableTiming);
        init_done = 1;
    }

    float  *x, *bqkv;
    __half *t1h, *xh, *qkvh, *ctxh, *ffh, *wch;
    cudaGetSymbolAddress((void**)&x,    g_x);
    cudaGetSymbolAddress((void**)&t1h,  g_t1h);
    cudaGetSymbolAddress((void**)&xh,   g_xh);
    cudaGetSymbolAddress((void**)&qkvh, g_qkv);
    cudaGetSymbolAddress((void**)&ctxh, g_ctxh);
    cudaGetSymbolAddress((void**)&ffh,  g_ffh);
    cudaGetSymbolAddress((void**)&wch,  g_wch);
    cudaGetSymbolAddress((void**)&bqkv, g_bqkv);

    const size_t DD = (size_t)Dq * Dq, DF = (size_t)Dq * FFq;
    __half* wc_qkv = wch;                        // [L][1024][3072] concat
    __half* wc_o   = wc_qkv + Lq * 3 * DD;
    __half* wc_1   = wc_o   + Lq * DD;           // W1 [D, FF]
    __half* wc_2   = wc_1   + Lq * DF;           // W2 [FF, D]

    const int n8dd  = (int)(Lq * DD / 8);
    const int gsall = n8dd / (256 * 4);
    const int n8df  = (int)(Lq * DF / 8);
    const int gf    = n8df / (256 * 4);
    const int n8l0  = (int)(DD / 8);
    const int g0    = n8l0 / (256 * 4);
    const int n8r   = n8dd - n8l0;
    const int gr    = n8r / (256 * 4);
    const size_t SRCL = DD / 4;
    const size_t DSTL = (size_t)1024 * 384;

    // ---- forked prologue
    cudaEventRecord(ev0, 0);
    cudaStreamWaitEvent(side, ev0, 0);

    embed_pe<<<(Mq * Dq) / 256, 256, 0, side>>>(src, emb, x, xh);
    bias_cat<<<(Lq * QKVN) / 256, 256, 0, side>>>(bqp, bkp, bvp, bqkv);
    cudaEventRecord(evA, side);
    wconv <<<gsall, 256, 0, side>>>((const float4*)Wop, (uint4*)wc_o, n8dd);
    wconvs<<<gr, 256, 0, side>>>((const float4*)Wqp + SRCL,
                                 (uint4*)wc_qkv + DSTL,       n8r);
    wconvs<<<gr, 256, 0, side>>>((const float4*)Wkp + SRCL,
                                 (uint4*)wc_qkv + DSTL + 128, n8r);
    wconvs<<<gr, 256, 0, side>>>((const float4*)Wvp + SRCL,
                                 (uint4*)wc_qkv + DSTL + 256, n8r);
    wconv <<<gf, 256, 0, side>>>((const float4*)W1p, (uint4*)wc_1, n8df);
    wconv <<<gf, 256, 0, side>>>((const float4*)W2p, (uint4*)wc_2, n8df);
    cudaEventRecord(evB, side);

    wconvs<<<g0, 256>>>((const float4*)Wqp, (uint4*)wc_qkv,       n8l0);
    wconvs<<<g0, 256>>>((const float4*)Wkp, (uint4*)wc_qkv + 128, n8l0);
    wconvs<<<g0, 256>>>((const float4*)Wvp, (uint4*)wc_qkv + 256, n8l0);
    cudaStreamWaitEvent(0, evA, 0);

    for (int l = 0; l < Lq; l++) {
        gemm(xh, Dq, wc_qkv + (size_t)l * 1024 * QKVN, QKVN,
             qkvh, QKVN, Mq, QKVN, Dq, bqkv + l * QKVN, 0);

        {
            dim3 grid(Sq / 128, Bq * Hq);
            flash_attn<<<grid, 256, FA_SMEM>>>(qkvh, qkvh + 1024, qkvh + 2048,
                                               mask, ctxh, QKVN);
        }

        if (l == 0)
            cudaStreamWaitEvent(0, evB, 0);

        gemm(ctxh, Dq, wc_o + l * DD, Dq, t1h, Dq, Mq, Dq, Dq, bop + l * Dq, 0);
        add_ln<<<Mq, 256>>>(t1h, x, l1s + l * Dq, l1b + l * Dq, x, xh);

        gemm(xh, Dq, wc_1 + l * DF, FFq, ffh, FFq, Mq, FFq, Dq, b1p + l * FFq, 1);
        gemm(ffh, FFq, wc_2 + l * DF, Dq, t1h, Dq, Mq, Dq, FFq, b2p + l * Dq, 0);
        add_ln<<<Mq, 256>>>(t1h, x, l2s + l * Dq, l2b + l * Dq,
                            (l == Lq - 1) ? out : x,
                            (l == Lq - 1) ? nullptr : xh);
    }
}

// round 15
// speedup vs baseline: 1.0334x; 1.0334x over previous
#include <cuda_runtime.h>
#include <cuda_fp16.h>
#include <math.h>
#include <stdint.h>

// Problem dims
#define Bq 4
#define Sq 1024
#define Dq 1024
#define Hq 16
#define HSq 64
#define FFq 4096
#define Lq 6
#define Mq (Bq*Sq)      // 4096 token rows
#define QKVN 3072       // merged QKV output width

// ---------------- scratch (static device memory; no allocations) ----------
__device__ float  g_x  [Mq*Dq];                      // fp32 residual stream
__device__ __half g_t1h[Mq*Dq];
__device__ __half g_xh [Mq*Dq];
__device__ __half g_qkv[(size_t)Mq*QKVN];            // merged q|k|v rows
__device__ __half g_ctxh[Mq*Dq];
__device__ __half g_ffh[(size_t)Mq*FFq];
__device__ __half g_wch[(size_t)Lq*(4*Dq*Dq + 2*Dq*FFq)];   // weights half
__device__ float  g_bqkv[Lq*QKVN];                   // concat qkv bias

// ---------------- helpers ---------------------------------------------------
__device__ __forceinline__ void mma16(float* d, const unsigned* a,
                                      unsigned b0, unsigned b1){
    asm volatile(
        "mma.sync.aligned.m16n8k16.row.col.f32.f16.f16.f32 "
        "{%0,%1,%2,%3},{%4,%5,%6,%7},{%8,%9},{%0,%1,%2,%3};\n"
        : "+f"(d[0]), "+f"(d[1]), "+f"(d[2]), "+f"(d[3])
        : "r"(a[0]), "r"(a[1]), "r"(a[2]), "r"(a[3]), "r"(b0), "r"(b1));
}

__device__ __forceinline__ void ldsm4(unsigned* r, unsigned addr){
    asm volatile("ldmatrix.sync.aligned.m8n8.x4.shared.b16 {%0,%1,%2,%3}, [%4];"
        : "=r"(r[0]), "=r"(r[1]), "=r"(r[2]), "=r"(r[3]) : "r"(addr));
}
__device__ __forceinline__ void ldsm4t(unsigned* r, unsigned addr){
    asm volatile("ldmatrix.sync.aligned.m8n8.x4.trans.shared.b16 {%0,%1,%2,%3}, [%4];"
        : "=r"(r[0]), "=r"(r[1]), "=r"(r[2]), "=r"(r[3]) : "r"(addr));
}

__device__ __forceinline__ void cp16(unsigned dst, const void* src){
    asm volatile("cp.async.cg.shared.global [%0], [%1], 16;\n" :: "r"(dst), "l"(src));
}
__device__ __forceinline__ void cp_commit(){ asm volatile("cp.async.commit_group;\n"); }
__device__ __forceinline__ unsigned smem_u32(const void* p){
    return (unsigned)__cvta_generic_to_shared(p);
}
__device__ __forceinline__ float ex2(float x){
    float r; asm("ex2.approx.ftz.f32 %0, %1;" : "=f"(r) : "f"(x)); return r;
}
__device__ __forceinline__ uint4 pack8(float4 a, float4 b){
    half2 h0 = __floats2half2_rn(a.x, a.y);
    half2 h1 = __floats2half2_rn(a.z, a.w);
    half2 h2 = __floats2half2_rn(b.x, b.y);
    half2 h3 = __floats2half2_rn(b.z, b.w);
    uint4 o;
    o.x = *(unsigned*)&h0; o.y = *(unsigned*)&h1;
    o.z = *(unsigned*)&h2; o.w = *(unsigned*)&h3;
    return o;
}

// ================== fused flash attention (no-max softmax, occ 2) ==========
#define QSTR 72
#define VSTR 72
#define FA_SMEM (128*QSTR*2 + 2*128*QSTR*2 + 2*128*VSTR*2 + 1024*4)

__global__ __launch_bounds__(256, 2)
void flash_attn(const __half* __restrict__ qh,
                const __half* __restrict__ kh,
                const __half* __restrict__ vh,
                const int*    __restrict__ mask,
                __half* __restrict__ ctxh,
                int ldq)
{
    extern __shared__ __align__(16) char fsm[];
    __half* Qs = (__half*)fsm;
    __half* Ks = Qs + 128 * QSTR;
    __half* Vs = Ks + 2 * 128 * QSTR;
    float*  ms = (float*)(Vs + 2 * 128 * VSTR);

    const int tid  = threadIdx.x;
    const int lane = tid & 31;
    const int w    = tid >> 5;
    const int g    = lane >> 2;
    const int t4   = lane & 3;
    const int grp  = lane >> 3;
    const int l8   = lane & 7;
    const int ofs1 = (grp & 1) * 8;
    const int ofs2 = (grp >> 1) * 8;
    const int bh = blockIdx.y;
    const int b  = bh >> 4, h = bh & 15;
    const int q0 = blockIdx.x * 128;
    const float SC = 0.125f * 1.44269504f;

    const unsigned qs = smem_u32(Qs), ks_ = smem_u32(Ks), vs_ = smem_u32(Vs);

    const size_t qbase = ((size_t)b * Sq + q0) * ldq + (size_t)h * HSq;
    #pragma unroll
    for (int c = 0; c < 4; c++) {
        int i = tid + c * 256, row = i >> 3, kc = (i & 7) * 8;
        cp16(qs + (unsigned)(row * QSTR + kc) * 2u,
             qh + qbase + (size_t)row * ldq + kc);
    }
    cp_commit();
    #pragma unroll
    for (int c = 0; c < 4; c++) {
        int i = tid + c * 256;
        ms[i] = mask[b * Sq + i] ? 0.f : -1.0e30f;
    }

    auto load_kv = [&](int kb, int st){
        const int kv0 = kb * 128;
        const size_t kbase = ((size_t)b * Sq + kv0) * ldq + (size_t)h * HSq;
        const unsigned kdst = ks_ + (unsigned)(st * 128 * QSTR) * 2u;
        const unsigned vdst = vs_ + (unsigned)(st * 128 * VSTR) * 2u;
        #pragma unroll
        for (int c = 0; c < 4; c++) {
            int i = tid + c * 256, row = i >> 3, kc = (i & 7) * 8;
            cp16(kdst + (unsigned)(row * QSTR + kc) * 2u,
                 kh + kbase + (size_t)row * ldq + kc);
        }
        #pragma unroll
        for (int c = 0; c < 4; c++) {
            int i = tid + c * 256, row = i >> 3, kc = (i & 7) * 8;
            cp16(vdst + (unsigned)(row * VSTR + kc) * 2u,
                 vh + kbase + (size_t)row * ldq + kc);
        }
        cp_commit();
    };

    load_kv(0, 0);

    asm volatile("cp.async.wait_group 1;\n");
    __syncthreads();

    unsigned qa[4][4];
    {
        const int rq = w * 16;
        #pragma unroll
        for (int ks = 0; ks < 4; ks++) {
            qa[ks][0] = *(const unsigned*)&Qs[(rq + g    ) * QSTR + ks*16 + 2*t4    ];
            qa[ks][1] = *(const unsigned*)&Qs[(rq + g + 8) * QSTR + ks*16 + 2*t4    ];
            qa[ks][2] = *(const unsigned*)&Qs[(rq + g    ) * QSTR + ks*16 + 2*t4 + 8];
            qa[ks][3] = *(const unsigned*)&Qs[(rq + g + 8) * QSTR + ks*16 + 2*t4 + 8];
        }
    }

    float O[8][4];
    #pragma unroll
    for (int t = 0; t < 8; t++)
        #pragma unroll
        for (int r = 0; r < 4; r++) O[t][r] = 0.f;
    float l0 = 0.f, l1 = 0.f;

    for (int kb = 0; kb < 8; kb++) {
        const int st = kb & 1;
        if (kb + 1 < 8) {
            load_kv(kb + 1, st ^ 1);
            asm volatile("cp.async.wait_group 1;\n");
        } else {
            asm volatile("cp.async.wait_group 0;\n");
        }
        __syncthreads();

        const unsigned K_ = ks_ + (unsigned)(st * 128 * QSTR) * 2u;
        const unsigned V_ = vs_ + (unsigned)(st * 128 * VSTR) * 2u;

        #pragma unroll
        for (int hf = 0; hf < 2; hf++) {
            float c[8][4];
            #pragma unroll
            for (int t = 0; t < 8; t++)
                #pragma unroll
                for (int r = 0; r < 4; r++) c[t][r] = 0.f;
            #pragma unroll
            for (int t2 = 0; t2 < 4; t2++) {
                const int t2g = hf * 4 + t2;
                unsigned kf[4][4];
                #pragma unroll
                for (int ks = 0; ks < 4; ks++)
                    ldsm4(kf[ks], K_ + (unsigned)((t2g*16 + ofs1 + l8) * QSTR
                                                  + ks*16 + ofs2) * 2u);
                #pragma unroll
                for (int ks = 0; ks < 4; ks++) {
                    mma16(c[2*t2    ], qa[ks], kf[ks][0], kf[ks][2]);
                    mma16(c[2*t2 + 1], qa[ks], kf[ks][1], kf[ks][3]);
                }
            }

            unsigned pa[4][4];
            #pragma unroll
            for (int t = 0; t < 8; t++) {
                const int tg = hf * 8 + t;
                float2 mb = *(const float2*)&ms[kb*128 + tg*8 + 2*t4];
                float p0 = ex2(c[t][0] * SC + mb.x);
                float p1 = ex2(c[t][1] * SC + mb.y);
                float p2 = ex2(c[t][2] * SC + mb.x);
                float p3 = ex2(c[t][3] * SC + mb.y);
                l0 += p0 + p1;  l1 += p2 + p3;
                half2 h01 = __floats2half2_rn(p0, p1);
                half2 h23 = __floats2half2_rn(p2, p3);
                const int ks = t >> 1, sub = (t & 1) * 2;
                pa[ks][sub    ] = *(unsigned*)&h01;
                pa[ks][sub + 1] = *(unsigned*)&h23;
            }

            #pragma unroll
            for (int ks = 0; ks < 4; ks++) {
                const int ksg = hf * 4 + ks;
                unsigned vf[4][4];
                #pragma unroll
                for (int h2 = 0; h2 < 4; h2++)
                    ldsm4t(vf[h2], V_ + (unsigned)((ksg*16 + ofs1 + l8) * VSTR
                                                   + h2*16 + ofs2) * 2u);
                #pragma unroll
                for (int h2 = 0; h2 < 4; h2++) {
                    mma16(O[2*h2    ], pa[ks], vf[h2][0], vf[h2][1]);
                    mma16(O[2*h2 + 1], pa[ks], vf[h2][2], vf[h2][3]);
                }
            }
        }
        __syncthreads();
    }

    l0 += __shfl_xor_sync(0xffffffffu, l0, 1);
    l0 += __shfl_xor_sync(0xffffffffu, l0, 2);
    l1 += __shfl_xor_sync(0xffffffffu, l1, 1);
    l1 += __shfl_xor_sync(0xffffffffu, l1, 2);
    const float r0 = 1.f / l0, r1 = 1.f / l1;
    const int row0 = q0 + w * 16 + g;
    #pragma unroll
    for (int t = 0; t < 8; t++) {
        half2 o01 = __floats2half2_rn(O[t][0] * r0, O[t][1] * r0);
        half2 o23 = __floats2half2_rn(O[t][2] * r1, O[t][3] * r1);
        size_t base = ((size_t)b * Sq + row0) * Dq + h * HSq + t*8 + 2*t4;
        *(half2*)&ctxh[base]          = o01;
        *(half2*)&ctxh[base + 8 * Dq] = o23;
    }
}

// ================== fp16 GEMM: A[M,K] @ B[K,N], BK=64, 2-stage (R13) ======
#define BM 128
#define BKh 64
#define ASTR 72
#define NSTRIDE 136
#define GH_A_STG (BM * ASTR * 2)
#define GH_B_STG (BKh * NSTRIDE * 2)
#define GH_SMEM (2*GH_A_STG + 2*GH_B_STG)

template<int BNt>
__global__ __launch_bounds__(256, 2)
void gemm_h(const __half* __restrict__ A, int lda,
            const __half* __restrict__ Bm, int ldb,
            __half* __restrict__ Ch, int ldc,
            int M, int N, int K,
            const float* __restrict__ bias, int relu)
{
    constexpr int NI   = BNt / 16;
    constexpr int NP   = NI / 2;
    constexpr int A_CP = (BM  * BKh) / (8 * 256);
    constexpr int B_CP = (BKh * BNt) / (8 * 256);

    extern __shared__ __align__(16) char gsm[];

    const int m0 = blockIdx.y * BM;
    const int n0 = blockIdx.x * BNt;
    const int tid  = threadIdx.x;
    const int lane = tid & 31;
    const int w    = tid >> 5;
    const int wm   = (w >> 1) * 32;
    const int wn   = (w & 1) * (BNt / 2);
    const int g    = lane >> 2;
    const int t4   = lane & 3;
    const int grp  = lane >> 3;
    const int l8   = lane & 7;
    const int ofs1 = (grp & 1) * 8;
    const int ofs2 = (grp >> 1) * 8;

    const unsigned sb = smem_u32(gsm);
    unsigned as_base[2], bs_base[2];
    as_base[0] = sb;                 as_base[1] = sb + GH_A_STG;
    bs_base[0] = sb + 2*GH_A_STG;    bs_base[1] = sb + 2*GH_A_STG + GH_B_STG;

    const unsigned a_off = (unsigned)((ofs1 + l8) * ASTR + ofs2);

    float acc[2][NI][4];
    #pragma unroll
    for (int mi = 0; mi < 2; mi++)
        #pragma unroll
        for (int ni = 0; ni < NI; ni++)
            #pragma unroll
            for (int r = 0; r < 4; r++) acc[mi][ni][r] = 0.f;

    const int niter = K / BKh;

    auto load_stage = [&](int it, int buf) {
        const long long k0 = (long long)it * BKh;
        #pragma unroll
        for (int c = 0; c < A_CP; c++) {
            int q = tid + c * 256, row = q >> 3, kc = (q & 7) * 8;
            cp16(as_base[buf] + (unsigned)(row * ASTR + kc) * 2u,
                 A + (size_t)(m0 + row) * lda + k0 + kc);
        }
        #pragma unroll
        for (int c = 0; c < B_CP; c++) {
            int q = tid + c * 256, row = q >> 4, cc = (q & 15) * 8;
            cp16(bs_base[buf] + (unsigned)(row * NSTRIDE + cc) * 2u,
                 Bm + (size_t)(k0 + row) * ldb + n0 + cc);
        }
        cp_commit();
    };

    load_stage(0, 0);

    for (int it = 0; it < niter; it++) {
        const int buf = it & 1;
        if (it + 1 < niter) {
            load_stage(it + 1, buf ^ 1);
            asm volatile("cp.async.wait_group 1;\n");
        } else {
            asm volatile("cp.async.wait_group 0;\n");
        }
        __syncthreads();

        const unsigned as_ = as_base[buf];
        const unsigned bs_ = bs_base[buf];

        #pragma unroll
        for (int kk = 0; kk < BKh; kk += 16) {
            unsigned a[2][4], bf[NP][4];
            #pragma unroll
            for (int mi = 0; mi < 2; mi++)
                ldsm4(a[mi], as_ + ((unsigned)((wm + mi*16) * ASTR + kk) + a_off) * 2u);
            #pragma unroll
            for (int np = 0; np < NP; np++)
                ldsm4t(bf[np], bs_ + (unsigned)((kk + ofs1 + l8) * NSTRIDE
                                                + wn + np*16 + ofs2) * 2u);
            #pragma unroll
            for (int mi = 0; mi < 2; mi++)
                #pragma unroll
                for (int np = 0; np < NP; np++) {
                    mma16(acc[mi][np*2    ], a[mi], bf[np][0], bf[np][1]);
                    mma16(acc[mi][np*2 + 1], a[mi], bf[np][2], bf[np][3]);
                }
        }
        __syncthreads();
    }

    #pragma unroll
    for (int mi = 0; mi < 2; mi++) {
        int r0 = m0 + wm + mi * 16 + g;
        #pragma unroll
        for (int ni = 0; ni < NI; ni++) {
            int c = n0 + wn + ni * 8 + t4 * 2;
            float2 bv = bias ? *(const float2*)&bias[c] : make_float2(0.f, 0.f);
            float v00 = acc[mi][ni][0] + bv.x;
            float v01 = acc[mi][ni][1] + bv.y;
            float v10 = acc[mi][ni][2] + bv.x;
            float v11 = acc[mi][ni][3] + bv.y;
            if (relu) {
                v00 = fmaxf(v00, 0.f); v01 = fmaxf(v01, 0.f);
                v10 = fmaxf(v10, 0.f); v11 = fmaxf(v11, 0.f);
            }
            *(half2*)&Ch[(size_t)r0 * ldc + c]       = __floats2half2_rn(v00, v01);
            *(half2*)&Ch[(size_t)(r0 + 8) * ldc + c] = __floats2half2_rn(v10, v11);
        }
    }
}

// ---------------- fp32 -> fp16 weight convert, contiguous (4x unrolled) ----
__global__ void wconv(const float4* __restrict__ src, uint4* __restrict__ dst,
                      int n8)
{
    const int S = gridDim.x * blockDim.x;
    int i = blockIdx.x * blockDim.x + threadIdx.x;
    float4 a0 = src[(size_t)i*2],           b0 = src[(size_t)i*2 + 1];
    float4 a1 = src[(size_t)(i+S)*2],       b1 = src[(size_t)(i+S)*2 + 1];
    float4 a2 = src[(size_t)(i+2*S)*2],     b2 = src[(size_t)(i+2*S)*2 + 1];
    float4 a3 = src[(size_t)(i+3*S)*2],     b3 = src[(size_t)(i+3*S)*2 + 1];
    dst[i      ] = pack8(a0, b0);
    dst[i +   S] = pack8(a1, b1);
    dst[i + 2*S] = pack8(a2, b2);
    dst[i + 3*S] = pack8(a3, b3);
}

// ---------------- fp32 -> fp16 weight convert into QKV-concat layout -------
__global__ void wconvs(const float4* __restrict__ src, uint4* __restrict__ dst,
                       int n8)
{
    const int S = gridDim.x * blockDim.x;
    int i = blockIdx.x * blockDim.x + threadIdx.x;
    #pragma unroll
    for (int u = 0; u < 4; u++) {
        int j = i + u * S;
        float4 a = src[(size_t)j*2], b = src[(size_t)j*2 + 1];
        dst[(size_t)(j >> 7) * 384 + (j & 127)] = pack8(a, b);
    }
}

// ---------------- concat qkv biases -----------------------------------------
__global__ void bias_cat(const float* __restrict__ bq,
                         const float* __restrict__ bk,
                         const float* __restrict__ bv,
                         float* __restrict__ o)
{
    int idx = blockIdx.x * 256 + threadIdx.x;        // Lq*3072 total
    int l = idx / QKVN, j = idx % QKVN;
    const float* s = (j < 1024) ? bq : (j < 2048) ? bk : bv;
    o[idx] = s[l * 1024 + (j & 1023)];
}

// ---------------- embedding + positional encoding (fp32 + half out) --------
__global__ void embed_pe(const int* __restrict__ src,
                         const float* __restrict__ emb,
                         float* __restrict__ x,
                         __half* __restrict__ xh)
{
    size_t i = (size_t)blockIdx.x * blockDim.x + threadIdx.x;
    int d  = (int)(i & (Dq - 1));
    size_t bs = i >> 10;
    int s  = (int)(bs & (Sq - 1));
    int tok = src[bs];
    float ex  = (float)(d & ~1) / (float)Dq;
    float inv = expf(-9.210340371976184f * ex);
    float ang = (float)s * inv;
    float pe  = (d & 1) ? cosf(ang) : sinf(ang);
    float v = emb[(size_t)tok * Dq + d] + pe;
    x[i]  = v;
    xh[i] = __float2half(v);
}

// ---------------- fused residual-add + LayerNorm (vectorized) --------------
__global__ void add_ln(const __half* __restrict__ a,
                       const float* __restrict__ xres,
                       const float* __restrict__ sc,
                       const float* __restrict__ sh,
                       float* __restrict__ out_f,
                       __half* __restrict__ out_h)
{
    __shared__ float r1[8], r2[8];
    const int row = blockIdx.x;
    const int tid = threadIdx.x;
    const int c0  = tid * 4;
    const __half* ar = a    + (size_t)row * Dq;
    const float*  xr = xres + (size_t)row * Dq;

    uint2 av = *(const uint2*)&ar[c0];
    half2 a01 = *(half2*)&av.x, a23 = *(half2*)&av.y;
    float4 xv = *(const float4*)&xr[c0];
    float v0 = __low2float(a01)  + xv.x;
    float v1 = __high2float(a01) + xv.y;
    float v2 = __low2float(a23)  + xv.z;
    float v3 = __high2float(a23) + xv.w;

    float sum = v0 + v1 + v2 + v3;
    float sq  = v0*v0 + v1*v1 + v2*v2 + v3*v3;
    #pragma unroll
    for (int o = 16; o; o >>= 1) {
        sum += __shfl_xor_sync(0xffffffffu, sum, o);
        sq  += __shfl_xor_sync(0xffffffffu, sq,  o);
    }
    if ((tid & 31) == 0) { r1[tid >> 5] = sum; r2[tid >> 5] = sq; }
    __syncthreads();
    sum = 0.f; sq = 0.f;
    #pragma unroll
    for (int i = 0; i < 8; i++) { sum += r1[i]; sq += r2[i]; }
    float mu  = sum * (1.f / Dq);
    float var = sq * (1.f / Dq) - mu * mu;
    float inv = rsqrtf(var + 1e-5f);

    float4 sv = *(const float4*)&sc[c0];
    float4 hv = *(const float4*)&sh[c0];
    float o0 = (v0 - mu) * inv * sv.x + hv.x;
    float o1 = (v1 - mu) * inv * sv.y + hv.y;
    float o2 = (v2 - mu) * inv * sv.z + hv.z;
    float o3 = (v3 - mu) * inv * sv.w + hv.w;

    *(float4*)&out_f[(size_t)row * Dq + c0] = make_float4(o0, o1, o2, o3);
    if (out_h) {
        half2 p0 = __floats2half2_rn(o0, o1);
        half2 p1 = __floats2half2_rn(o2, o3);
        uint2 pv; pv.x = *(unsigned*)&p0; pv.y = *(unsigned*)&p1;
        *(uint2*)&out_h[(size_t)row * Dq + c0] = pv;
    }
}

// ---------------- host-side GEMM launcher -----------------------------------
static void gemm(const __half* A, int lda, const __half* Bm, int ldb,
                 __half* Ch, int ldc, int M, int N, int K,
                 const float* bias, int relu)
{
    dim3 grid(N / 128, M / BM, 1);
    gemm_h<128><<<grid, 256, GH_SMEM>>>(A, lda, Bm, ldb, Ch, ldc, M, N, K,
                                        bias, relu);
}

// ---------------- entry point ------------------------------------------------
extern "C" void kernel_launch(void* const* d_in, const int* in_sizes, int n_in,
                              void* d_out, int out_size)
{
    const int*   src  = (const int*)  d_in[0];
    const int*   mask = (const int*)  d_in[1];
    const float* emb  = (const float*)d_in[2];
    const float* Wqp  = (const float*)d_in[3];
    const float* bqp  = (const float*)d_in[4];
    const float* Wkp  = (const float*)d_in[5];
    const float* bkp  = (const float*)d_in[6];
    const float* Wvp  = (const float*)d_in[7];
    const float* bvp  = (const float*)d_in[8];
    const float* Wop  = (const float*)d_in[9];
    const float* bop  = (const float*)d_in[10];
    const float* l1s  = (const float*)d_in[11];
    const float* l1b  = (const float*)d_in[12];
    const float* W1p  = (const float*)d_in[13];
    const float* b1p  = (const float*)d_in[14];
    const float* W2p  = (const float*)d_in[15];
    const float* b2p  = (const float*)d_in[16];
    const float* l2s  = (const float*)d_in[17];
    const float* l2b  = (const float*)d_in[18];
    float* out = (float*)d_out;

    static int init_done = 0;
    static cudaStream_t side = nullptr;
    static cudaEvent_t ev0 = nullptr, evA = nullptr, evB = nullptr;
    if (!init_done) {
        cudaFuncSetAttribute(flash_attn,
                             cudaFuncAttributeMaxDynamicSharedMemorySize, FA_SMEM);
        cudaFuncSetAttribute(gemm_h<128>,
                             cudaFuncAttributeMaxDynamicSharedMemorySize, GH_SMEM);
        cudaStreamCreateWithFlags(&side, cudaStreamNonBlocking);
        cudaEventCreateWithFlags(&ev0, cudaEventDisableTiming);
        cudaEventCreateWithFlags(&evA, cudaEventDisableTiming);
        cudaEventCreateWithFlags(&evB, cudaEventDisableTiming);
        init_done = 1;
    }

    float  *x, *bqkv;
    __half *t1h, *xh, *qkvh, *ctxh, *ffh, *wch;
    cudaGetSymbolAddress((void**)&x,    g_x);
    cudaGetSymbolAddress((void**)&t1h,  g_t1h);
    cudaGetSymbolAddress((void**)&xh,   g_xh);
    cudaGetSymbolAddress((void**)&qkvh, g_qkv);
    cudaGetSymbolAddress((void**)&ctxh, g_ctxh);
    cudaGetSymbolAddress((void**)&ffh,  g_ffh);
    cudaGetSymbolAddress((void**)&wch,  g_wch);
    cudaGetSymbolAddress((void**)&bqkv, g_bqkv);

    const size_t DD = (size_t)Dq * Dq, DF = (size_t)Dq * FFq;
    __half* wc_qkv = wch;                        // [L][1024][3072] concat
    __half* wc_o   = wc_qkv + Lq * 3 * DD;
    __half* wc_1   = wc_o   + Lq * DD;           // W1 [D, FF]
    __half* wc_2   = wc_1   + Lq * DF;           // W2 [FF, D]

    const int n8dd  = (int)(Lq * DD / 8);
    const int gsall = n8dd / (256 * 4);
    const int n8df  = (int)(Lq * DF / 8);
    const int gf    = n8df / (256 * 4);
    const int n8l0  = (int)(DD / 8);
    const int g0    = n8l0 / (256 * 4);
    const int n8r   = n8dd - n8l0;
    const int gr    = n8r / (256 * 4);
    const size_t SRCL = DD / 4;
    const size_t DSTL = (size_t)1024 * 384;

    // ---- forked prologue
    cudaEventRecord(ev0, 0);
    cudaStreamWaitEvent(side, ev0, 0);

    embed_pe<<<(Mq * Dq) / 256, 256, 0, side>>>(src, emb, x, xh);
    bias_cat<<<(Lq * QKVN) / 256, 256, 0, side>>>(bqp, bkp, bvp, bqkv);
    cudaEventRecord(evA, side);
    wconv <<<gsall, 256, 0, side>>>((const float4*)Wop, (uint4*)wc_o, n8dd);
    wconvs<<<gr, 256, 0, side>>>((const float4*)Wqp + SRCL,
                                 (uint4*)wc_qkv + DSTL,       n8r);
    wconvs<<<gr, 256, 0, side>>>((const float4*)Wkp + SRCL,
                                 (uint4*)wc_qkv + DSTL + 128, n8r);
    wconvs<<<gr, 256, 0, side>>>((const float4*)Wvp + SRCL,
                                 (uint4*)wc_qkv + DSTL + 256, n8r);
    wconv <<<gf, 256, 0, side>>>((const float4*)W1p, (uint4*)wc_1, n8df);
    wconv <<<gf, 256, 0, side>>>((const float4*)W2p, (uint4*)wc_2, n8df);
    cudaEventRecord(evB, side);

    wconvs<<<g0, 256>>>((const float4*)Wqp, (uint4*)wc_qkv,       n8l0);
    wconvs<<<g0, 256>>>((const float4*)Wkp, (uint4*)wc_qkv + 128, n8l0);
    wconvs<<<g0, 256>>>((const float4*)Wvp, (uint4*)wc_qkv + 256, n8l0);
    cudaStreamWaitEvent(0, evA, 0);

    for (int l = 0; l < Lq; l++) {
        gemm(xh, Dq, wc_qkv + (size_t)l * 1024 * QKVN, QKVN,
             qkvh, QKVN, Mq, QKVN, Dq, bqkv + l * QKVN, 0);

        {
            dim3 grid(Sq / 128, Bq * Hq);
            flash_attn<<<grid, 256, FA_SMEM>>>(qkvh, qkvh + 1024, qkvh + 2048,
                                               mask, ctxh, QKVN);
        }

        if (l == 0)
            cudaStreamWaitEvent(0, evB, 0);

        gemm(ctxh, Dq, wc_o + l * DD, Dq, t1h, Dq, Mq, Dq, Dq, bop + l * Dq, 0);
        add_ln<<<Mq, 256>>>(t1h, x, l1s + l * Dq, l1b + l * Dq, x, xh);

        gemm(xh, Dq, wc_1 + l * DF, FFq, ffh, FFq, Mq, FFq, Dq, b1p + l * FFq, 1);
        gemm(ffh, FFq, wc_2 + l * DF, Dq, t1h, Dq, Mq, Dq, FFq, b2p + l * Dq, 0);
        add_ln<<<Mq, 256>>>(t1h, x, l2s + l * Dq, l2b + l * Dq,
                            (l == Lq - 1) ? out : x,
                            (l == Lq - 1) ? nullptr : xh);
    }
}

// round 16
// speedup vs baseline: 1.0412x; 1.0075x over previous
#include <cuda_runtime.h>
#include <cuda_fp16.h>
#include <math.h>
#include <stdint.h>

// Problem dims
#define Bq 4
#define Sq 1024
#define Dq 1024
#define Hq 16
#define HSq 64
#define FFq 4096
#define Lq 6
#define Mq (Bq*Sq)      // 4096 token rows
#define QKVN 3072       // merged QKV output width

// ---------------- scratch (static device memory; no allocations) ----------
__device__ __half g_t1h[Mq*Dq];
__device__ __half g_xh [Mq*Dq];                      // half residual stream
__device__ __half g_qkv[(size_t)Mq*QKVN];            // merged q|k|v rows
__device__ __half g_ctxh[Mq*Dq];
__device__ __half g_ffh[(size_t)Mq*FFq];
__device__ __half g_wch[(size_t)Lq*(4*Dq*Dq + 2*Dq*FFq)];   // weights half
__device__ float  g_bqkv[Lq*QKVN];                   // concat qkv bias

// ---------------- helpers ---------------------------------------------------
__device__ __forceinline__ void mma16(float* d, const unsigned* a,
                                      unsigned b0, unsigned b1){
    asm volatile(
        "mma.sync.aligned.m16n8k16.row.col.f32.f16.f16.f32 "
        "{%0,%1,%2,%3},{%4,%5,%6,%7},{%8,%9},{%0,%1,%2,%3};\n"
        : "+f"(d[0]), "+f"(d[1]), "+f"(d[2]), "+f"(d[3])
        : "r"(a[0]), "r"(a[1]), "r"(a[2]), "r"(a[3]), "r"(b0), "r"(b1));
}

__device__ __forceinline__ void ldsm4(unsigned* r, unsigned addr){
    asm volatile("ldmatrix.sync.aligned.m8n8.x4.shared.b16 {%0,%1,%2,%3}, [%4];"
        : "=r"(r[0]), "=r"(r[1]), "=r"(r[2]), "=r"(r[3]) : "r"(addr));
}
__device__ __forceinline__ void ldsm4t(unsigned* r, unsigned addr){
    asm volatile("ldmatrix.sync.aligned.m8n8.x4.trans.shared.b16 {%0,%1,%2,%3}, [%4];"
        : "=r"(r[0]), "=r"(r[1]), "=r"(r[2]), "=r"(r[3]) : "r"(addr));
}

__device__ __forceinline__ void cp16(unsigned dst, const void* src){
    asm volatile("cp.async.cg.shared.global [%0], [%1], 16;\n" :: "r"(dst), "l"(src));
}
__device__ __forceinline__ void cp_commit(){ asm volatile("cp.async.commit_group;\n"); }
__device__ __forceinline__ unsigned smem_u32(const void* p){
    return (unsigned)__cvta_generic_to_shared(p);
}
__device__ __forceinline__ float ex2(float x){
    float r; asm("ex2.approx.ftz.f32 %0, %1;" : "=f"(r) : "f"(x)); return r;
}
__device__ __forceinline__ uint4 pack8(float4 a, float4 b){
    half2 h0 = __floats2half2_rn(a.x, a.y);
    half2 h1 = __floats2half2_rn(a.z, a.w);
    half2 h2 = __floats2half2_rn(b.x, b.y);
    half2 h3 = __floats2half2_rn(b.z, b.w);
    uint4 o;
    o.x = *(unsigned*)&h0; o.y = *(unsigned*)&h1;
    o.z = *(unsigned*)&h2; o.w = *(unsigned*)&h3;
    return o;
}

// ================== fused flash attention (no-max softmax, occ 2) ==========
#define QSTR 72
#define VSTR 72
#define FA_SMEM (128*QSTR*2 + 2*128*QSTR*2 + 2*128*VSTR*2 + 1024*4)

__global__ __launch_bounds__(256, 2)
void flash_attn(const __half* __restrict__ qh,
                const __half* __restrict__ kh,
                const __half* __restrict__ vh,
                const int*    __restrict__ mask,
                __half* __restrict__ ctxh,
                int ldq)
{
    extern __shared__ __align__(16) char fsm[];
    __half* Qs = (__half*)fsm;
    __half* Ks = Qs + 128 * QSTR;
    __half* Vs = Ks + 2 * 128 * QSTR;
    float*  ms = (float*)(Vs + 2 * 128 * VSTR);

    const int tid  = threadIdx.x;
    const int lane = tid & 31;
    const int w    = tid >> 5;
    const int g    = lane >> 2;
    const int t4   = lane & 3;
    const int grp  = lane >> 3;
    const int l8   = lane & 7;
    const int ofs1 = (grp & 1) * 8;
    const int ofs2 = (grp >> 1) * 8;
    const int bh = blockIdx.y;
    const int b  = bh >> 4, h = bh & 15;
    const int q0 = blockIdx.x * 128;
    const float SC = 0.125f * 1.44269504f;

    const unsigned qs = smem_u32(Qs), ks_ = smem_u32(Ks), vs_ = smem_u32(Vs);

    const size_t qbase = ((size_t)b * Sq + q0) * ldq + (size_t)h * HSq;
    #pragma unroll
    for (int c = 0; c < 4; c++) {
        int i = tid + c * 256, row = i >> 3, kc = (i & 7) * 8;
        cp16(qs + (unsigned)(row * QSTR + kc) * 2u,
             qh + qbase + (size_t)row * ldq + kc);
    }
    cp_commit();
    #pragma unroll
    for (int c = 0; c < 4; c++) {
        int i = tid + c * 256;
        ms[i] = mask[b * Sq + i] ? 0.f : -1.0e30f;
    }

    auto load_kv = [&](int kb, int st){
        const int kv0 = kb * 128;
        const size_t kbase = ((size_t)b * Sq + kv0) * ldq + (size_t)h * HSq;
        const unsigned kdst = ks_ + (unsigned)(st * 128 * QSTR) * 2u;
        const unsigned vdst = vs_ + (unsigned)(st * 128 * VSTR) * 2u;
        #pragma unroll
        for (int c = 0; c < 4; c++) {
            int i = tid + c * 256, row = i >> 3, kc = (i & 7) * 8;
            cp16(kdst + (unsigned)(row * QSTR + kc) * 2u,
                 kh + kbase + (size_t)row * ldq + kc);
        }
        #pragma unroll
        for (int c = 0; c < 4; c++) {
            int i = tid + c * 256, row = i >> 3, kc = (i & 7) * 8;
            cp16(vdst + (unsigned)(row * VSTR + kc) * 2u,
                 vh + kbase + (size_t)row * ldq + kc);
        }
        cp_commit();
    };

    load_kv(0, 0);

    asm volatile("cp.async.wait_group 1;\n");
    __syncthreads();

    unsigned qa[4][4];
    {
        const int rq = w * 16;
        #pragma unroll
        for (int ks = 0; ks < 4; ks++) {
            qa[ks][0] = *(const unsigned*)&Qs[(rq + g    ) * QSTR + ks*16 + 2*t4    ];
            qa[ks][1] = *(const unsigned*)&Qs[(rq + g + 8) * QSTR + ks*16 + 2*t4    ];
            qa[ks][2] = *(const unsigned*)&Qs[(rq + g    ) * QSTR + ks*16 + 2*t4 + 8];
            qa[ks][3] = *(const unsigned*)&Qs[(rq + g + 8) * QSTR + ks*16 + 2*t4 + 8];
        }
    }

    float O[8][4];
    #pragma unroll
    for (int t = 0; t < 8; t++)
        #pragma unroll
        for (int r = 0; r < 4; r++) O[t][r] = 0.f;
    float l0 = 0.f, l1 = 0.f;

    for (int kb = 0; kb < 8; kb++) {
        const int st = kb & 1;
        if (kb + 1 < 8) {
            load_kv(kb + 1, st ^ 1);
            asm volatile("cp.async.wait_group 1;\n");
        } else {
            asm volatile("cp.async.wait_group 0;\n");
        }
        __syncthreads();

        const unsigned K_ = ks_ + (unsigned)(st * 128 * QSTR) * 2u;
        const unsigned V_ = vs_ + (unsigned)(st * 128 * VSTR) * 2u;

        #pragma unroll
        for (int hf = 0; hf < 2; hf++) {
            float c[8][4];
            #pragma unroll
            for (int t = 0; t < 8; t++)
                #pragma unroll
                for (int r = 0; r < 4; r++) c[t][r] = 0.f;
            #pragma unroll
            for (int t2 = 0; t2 < 4; t2++) {
                const int t2g = hf * 4 + t2;
                unsigned kf[4][4];
                #pragma unroll
                for (int ks = 0; ks < 4; ks++)
                    ldsm4(kf[ks], K_ + (unsigned)((t2g*16 + ofs1 + l8) * QSTR
                                                  + ks*16 + ofs2) * 2u);
                #pragma unroll
                for (int ks = 0; ks < 4; ks++) {
                    mma16(c[2*t2    ], qa[ks], kf[ks][0], kf[ks][2]);
                    mma16(c[2*t2 + 1], qa[ks], kf[ks][1], kf[ks][3]);
                }
            }

            unsigned pa[4][4];
            #pragma unroll
            for (int t = 0; t < 8; t++) {
                const int tg = hf * 8 + t;
                float2 mb = *(const float2*)&ms[kb*128 + tg*8 + 2*t4];
                float p0 = ex2(c[t][0] * SC + mb.x);
                float p1 = ex2(c[t][1] * SC + mb.y);
                float p2 = ex2(c[t][2] * SC + mb.x);
                float p3 = ex2(c[t][3] * SC + mb.y);
                l0 += p0 + p1;  l1 += p2 + p3;
                half2 h01 = __floats2half2_rn(p0, p1);
                half2 h23 = __floats2half2_rn(p2, p3);
                const int ks = t >> 1, sub = (t & 1) * 2;
                pa[ks][sub    ] = *(unsigned*)&h01;
                pa[ks][sub + 1] = *(unsigned*)&h23;
            }

            #pragma unroll
            for (int ks = 0; ks < 4; ks++) {
                const int ksg = hf * 4 + ks;
                unsigned vf[4][4];
                #pragma unroll
                for (int h2 = 0; h2 < 4; h2++)
                    ldsm4t(vf[h2], V_ + (unsigned)((ksg*16 + ofs1 + l8) * VSTR
                                                   + h2*16 + ofs2) * 2u);
                #pragma unroll
                for (int h2 = 0; h2 < 4; h2++) {
                    mma16(O[2*h2    ], pa[ks], vf[h2][0], vf[h2][1]);
                    mma16(O[2*h2 + 1], pa[ks], vf[h2][2], vf[h2][3]);
                }
            }
        }
        __syncthreads();
    }

    l0 += __shfl_xor_sync(0xffffffffu, l0, 1);
    l0 += __shfl_xor_sync(0xffffffffu, l0, 2);
    l1 += __shfl_xor_sync(0xffffffffu, l1, 1);
    l1 += __shfl_xor_sync(0xffffffffu, l1, 2);
    const float r0 = 1.f / l0, r1 = 1.f / l1;
    const int row0 = q0 + w * 16 + g;
    #pragma unroll
    for (int t = 0; t < 8; t++) {
        half2 o01 = __floats2half2_rn(O[t][0] * r0, O[t][1] * r0);
        half2 o23 = __floats2half2_rn(O[t][2] * r1, O[t][3] * r1);
        size_t base = ((size_t)b * Sq + row0) * Dq + h * HSq + t*8 + 2*t4;
        *(half2*)&ctxh[base]          = o01;
        *(half2*)&ctxh[base + 8 * Dq] = o23;
    }
}

// ================== fp16 GEMM: A[M,K] @ B[K,N], BK=64, 2-stage =============
#define BM 128
#define BKh 64
#define ASTR 72
#define NSTRIDE 136
#define GH_A_STG (BM * ASTR * 2)
#define GH_B_STG (BKh * NSTRIDE * 2)
#define GH_SMEM (2*GH_A_STG + 2*GH_B_STG)

template<int BNt>
__global__ __launch_bounds__(256, 2)
void gemm_h(const __half* __restrict__ A, int lda,
            const __half* __restrict__ Bm, int ldb,
            __half* __restrict__ Ch, int ldc,
            int M, int N, int K,
            const float* __restrict__ bias, int relu)
{
    constexpr int NI   = BNt / 16;
    constexpr int NP   = NI / 2;
    constexpr int A_CP = (BM  * BKh) / (8 * 256);
    constexpr int B_CP = (BKh * BNt) / (8 * 256);

    extern __shared__ __align__(16) char gsm[];

    const int m0 = blockIdx.y * BM;
    const int n0 = blockIdx.x * BNt;
    const int tid  = threadIdx.x;
    const int lane = tid & 31;
    const int w    = tid >> 5;
    const int wm   = (w >> 1) * 32;
    const int wn   = (w & 1) * (BNt / 2);
    const int g    = lane >> 2;
    const int t4   = lane & 3;
    const int grp  = lane >> 3;
    const int l8   = lane & 7;
    const int ofs1 = (grp & 1) * 8;
    const int ofs2 = (grp >> 1) * 8;

    const unsigned sb = smem_u32(gsm);
    unsigned as_base[2], bs_base[2];
    as_base[0] = sb;                 as_base[1] = sb + GH_A_STG;
    bs_base[0] = sb + 2*GH_A_STG;    bs_base[1] = sb + 2*GH_A_STG + GH_B_STG;

    const unsigned a_off = (unsigned)((ofs1 + l8) * ASTR + ofs2);

    float acc[2][NI][4];
    #pragma unroll
    for (int mi = 0; mi < 2; mi++)
        #pragma unroll
        for (int ni = 0; ni < NI; ni++)
            #pragma unroll
            for (int r = 0; r < 4; r++) acc[mi][ni][r] = 0.f;

    const int niter = K / BKh;

    auto load_stage = [&](int it, int buf) {
        const long long k0 = (long long)it * BKh;
        #pragma unroll
        for (int c = 0; c < A_CP; c++) {
            int q = tid + c * 256, row = q >> 3, kc = (q & 7) * 8;
            cp16(as_base[buf] + (unsigned)(row * ASTR + kc) * 2u,
                 A + (size_t)(m0 + row) * lda + k0 + kc);
        }
        #pragma unroll
        for (int c = 0; c < B_CP; c++) {
            int q = tid + c * 256, row = q >> 4, cc = (q & 15) * 8;
            cp16(bs_base[buf] + (unsigned)(row * NSTRIDE + cc) * 2u,
                 Bm + (size_t)(k0 + row) * ldb + n0 + cc);
        }
        cp_commit();
    };

    load_stage(0, 0);

    for (int it = 0; it < niter; it++) {
        const int buf = it & 1;
        if (it + 1 < niter) {
            load_stage(it + 1, buf ^ 1);
            asm volatile("cp.async.wait_group 1;\n");
        } else {
            asm volatile("cp.async.wait_group 0;\n");
        }
        __syncthreads();

        const unsigned as_ = as_base[buf];
        const unsigned bs_ = bs_base[buf];

        #pragma unroll
        for (int kk = 0; kk < BKh; kk += 16) {
            unsigned a[2][4], bf[NP][4];
            #pragma unroll
            for (int mi = 0; mi < 2; mi++)
                ldsm4(a[mi], as_ + ((unsigned)((wm + mi*16) * ASTR + kk) + a_off) * 2u);
            #pragma unroll
            for (int np = 0; np < NP; np++)
                ldsm4t(bf[np], bs_ + (unsigned)((kk + ofs1 + l8) * NSTRIDE
                                                + wn + np*16 + ofs2) * 2u);
            #pragma unroll
            for (int mi = 0; mi < 2; mi++)
                #pragma unroll
                for (int np = 0; np < NP; np++) {
                    mma16(acc[mi][np*2    ], a[mi], bf[np][0], bf[np][1]);
                    mma16(acc[mi][np*2 + 1], a[mi], bf[np][2], bf[np][3]);
                }
        }
        __syncthreads();
    }

    #pragma unroll
    for (int mi = 0; mi < 2; mi++) {
        int r0 = m0 + wm + mi * 16 + g;
        #pragma unroll
        for (int ni = 0; ni < NI; ni++) {
            int c = n0 + wn + ni * 8 + t4 * 2;
            float2 bv = bias ? *(const float2*)&bias[c] : make_float2(0.f, 0.f);
            float v00 = acc[mi][ni][0] + bv.x;
            float v01 = acc[mi][ni][1] + bv.y;
            float v10 = acc[mi][ni][2] + bv.x;
            float v11 = acc[mi][ni][3] + bv.y;
            if (relu) {
                v00 = fmaxf(v00, 0.f); v01 = fmaxf(v01, 0.f);
                v10 = fmaxf(v10, 0.f); v11 = fmaxf(v11, 0.f);
            }
            *(half2*)&Ch[(size_t)r0 * ldc + c]       = __floats2half2_rn(v00, v01);
            *(half2*)&Ch[(size_t)(r0 + 8) * ldc + c] = __floats2half2_rn(v10, v11);
        }
    }
}

// ---------------- fp32 -> fp16 weight convert, contiguous (4x unrolled) ----
__global__ void wconv(const float4* __restrict__ src, uint4* __restrict__ dst,
                      int n8)
{
    const int S = gridDim.x * blockDim.x;
    int i = blockIdx.x * blockDim.x + threadIdx.x;
    float4 a0 = src[(size_t)i*2],           b0 = src[(size_t)i*2 + 1];
    float4 a1 = src[(size_t)(i+S)*2],       b1 = src[(size_t)(i+S)*2 + 1];
    float4 a2 = src[(size_t)(i+2*S)*2],     b2 = src[(size_t)(i+2*S)*2 + 1];
    float4 a3 = src[(size_t)(i+3*S)*2],     b3 = src[(size_t)(i+3*S)*2 + 1];
    dst[i      ] = pack8(a0, b0);
    dst[i +   S] = pack8(a1, b1);
    dst[i + 2*S] = pack8(a2, b2);
    dst[i + 3*S] = pack8(a3, b3);
}

// ---------------- fp32 -> fp16 weight convert into QKV-concat layout -------
__global__ void wconvs(const float4* __restrict__ src, uint4* __restrict__ dst,
                       int n8)
{
    const int S = gridDim.x * blockDim.x;
    int i = blockIdx.x * blockDim.x + threadIdx.x;
    #pragma unroll
    for (int u = 0; u < 4; u++) {
        int j = i + u * S;
        float4 a = src[(size_t)j*2], b = src[(size_t)j*2 + 1];
        dst[(size_t)(j >> 7) * 384 + (j & 127)] = pack8(a, b);
    }
}

// ---------------- concat qkv biases -----------------------------------------
__global__ void bias_cat(const float* __restrict__ bq,
                         const float* __restrict__ bk,
                         const float* __restrict__ bv,
                         float* __restrict__ o)
{
    int idx = blockIdx.x * 256 + threadIdx.x;        // Lq*3072 total
    int l = idx / QKVN, j = idx % QKVN;
    const float* s = (j < 1024) ? bq : (j < 2048) ? bk : bv;
    o[idx] = s[l * 1024 + (j & 1023)];
}

// ---------------- embedding + positional encoding (half out) ---------------
__global__ void embed_pe(const int* __restrict__ src,
                         const float* __restrict__ emb,
                         __half* __restrict__ xh)
{
    size_t i = (size_t)blockIdx.x * blockDim.x + threadIdx.x;
    int d  = (int)(i & (Dq - 1));
    size_t bs = i >> 10;
    int s  = (int)(bs & (Sq - 1));
    int tok = src[bs];
    float ex  = (float)(d & ~1) / (float)Dq;
    float inv = expf(-9.210340371976184f * ex);
    float ang = (float)s * inv;
    float pe  = (d & 1) ? cosf(ang) : sinf(ang);
    xh[i] = __float2half(emb[(size_t)tok * Dq + d] + pe);
}

// ---------------- fused residual-add + LayerNorm (half streams, vectorized) -
__global__ void add_ln(const __half* __restrict__ a,      // projection (half)
                       const __half* __restrict__ xres,   // residual (half)
                       const float* __restrict__ sc,
                       const float* __restrict__ sh,
                       __half* __restrict__ out_h,        // half out (or null)
                       float*  __restrict__ out_f)        // fp32 out (final only)
{
    __shared__ float r1[8], r2[8];
    const int row = blockIdx.x;
    const int tid = threadIdx.x;
    const int c0  = tid * 4;
    const __half* ar = a    + (size_t)row * Dq;
    const __half* xr = xres + (size_t)row * Dq;

    uint2 av = *(const uint2*)&ar[c0];
    uint2 xv = *(const uint2*)&xr[c0];
    half2 a01 = *(half2*)&av.x, a23 = *(half2*)&av.y;
    half2 x01 = *(half2*)&xv.x, x23 = *(half2*)&xv.y;
    float v0 = __low2float(a01)  + __low2float(x01);
    float v1 = __high2float(a01) + __high2float(x01);
    float v2 = __low2float(a23)  + __low2float(x23);
    float v3 = __high2float(a23) + __high2float(x23);

    float sum = v0 + v1 + v2 + v3;
    float sq  = v0*v0 + v1*v1 + v2*v2 + v3*v3;
    #pragma unroll
    for (int o = 16; o; o >>= 1) {
        sum += __shfl_xor_sync(0xffffffffu, sum, o);
        sq  += __shfl_xor_sync(0xffffffffu, sq,  o);
    }
    if ((tid & 31) == 0) { r1[tid >> 5] = sum; r2[tid >> 5] = sq; }
    __syncthreads();
    sum = 0.f; sq = 0.f;
    #pragma unroll
    for (int i = 0; i < 8; i++) { sum += r1[i]; sq += r2[i]; }
    float mu  = sum * (1.f / Dq);
    float var = sq * (1.f / Dq) - mu * mu;
    float inv = rsqrtf(var + 1e-5f);

    float4 sv = *(const float4*)&sc[c0];
    float4 hv = *(const float4*)&sh[c0];
    float o0 = (v0 - mu) * inv * sv.x + hv.x;
    float o1 = (v1 - mu) * inv * sv.y + hv.y;
    float o2 = (v2 - mu) * inv * sv.z + hv.z;
    float o3 = (v3 - mu) * inv * sv.w + hv.w;

    if (out_h) {
        half2 p0 = __floats2half2_rn(o0, o1);
        half2 p1 = __floats2half2_rn(o2, o3);
        uint2 pv; pv.x = *(unsigned*)&p0; pv.y = *(unsigned*)&p1;
        *(uint2*)&out_h[(size_t)row * Dq + c0] = pv;
    }
    if (out_f)
        *(float4*)&out_f[(size_t)row * Dq + c0] = make_float4(o0, o1, o2, o3);
}

// ---------------- host-side GEMM launcher -----------------------------------
static void gemm(const __half* A, int lda, const __half* Bm, int ldb,
                 __half* Ch, int ldc, int M, int N, int K,
                 const float* bias, int relu)
{
    dim3 grid(N / 128, M / BM, 1);
    gemm_h<128><<<grid, 256, GH_SMEM>>>(A, lda, Bm, ldb, Ch, ldc, M, N, K,
                                        bias, relu);
}

// ---------------- entry point ------------------------------------------------
extern "C" void kernel_launch(void* const* d_in, const int* in_sizes, int n_in,
                              void* d_out, int out_size)
{
    const int*   src  = (const int*)  d_in[0];
    const int*   mask = (const int*)  d_in[1];
    const float* emb  = (const float*)d_in[2];
    const float* Wqp  = (const float*)d_in[3];
    const float* bqp  = (const float*)d_in[4];
    const float* Wkp  = (const float*)d_in[5];
    const float* bkp  = (const float*)d_in[6];
    const float* Wvp  = (const float*)d_in[7];
    const float* bvp  = (const float*)d_in[8];
    const float* Wop  = (const float*)d_in[9];
    const float* bop  = (const float*)d_in[10];
    const float* l1s  = (const float*)d_in[11];
    const float* l1b  = (const float*)d_in[12];
    const float* W1p  = (const float*)d_in[13];
    const float* b1p  = (const float*)d_in[14];
    const float* W2p  = (const float*)d_in[15];
    const float* b2p  = (const float*)d_in[16];
    const float* l2s  = (const float*)d_in[17];
    const float* l2b  = (const float*)d_in[18];
    float* out = (float*)d_out;

    static int init_done = 0;
    static cudaStream_t side = nullptr;
    static cudaEvent_t ev0 = nullptr, evA = nullptr, evB = nullptr;
    if (!init_done) {
        cudaFuncSetAttribute(flash_attn,
                             cudaFuncAttributeMaxDynamicSharedMemorySize, FA_SMEM);
        cudaFuncSetAttribute(gemm_h<128>,
                             cudaFuncAttributeMaxDynamicSharedMemorySize, GH_SMEM);
        cudaStreamCreateWithFlags(&side, cudaStreamNonBlocking);
        cudaEventCreateWithFlags(&ev0, cudaEventDisableTiming);
        cudaEventCreateWithFlags(&evA, cudaEventDisableTiming);
        cudaEventCreateWithFlags(&evB, cudaEventDisableTiming);
        init_done = 1;
    }

    float  *bqkv;
    __half *t1h, *xh, *qkvh, *ctxh, *ffh, *wch;
    cudaGetSymbolAddress((void**)&t1h,  g_t1h);
    cudaGetSymbolAddress((void**)&xh,   g_xh);
    cudaGetSymbolAddress((void**)&qkvh, g_qkv);
    cudaGetSymbolAddress((void**)&ctxh, g_ctxh);
    cudaGetSymbolAddress((void**)&ffh,  g_ffh);
    cudaGetSymbolAddress((void**)&wch,  g_wch);
    cudaGetSymbolAddress((void**)&bqkv, g_bqkv);

    const size_t DD = (size_t)Dq * Dq, DF = (size_t)Dq * FFq;
    __half* wc_qkv = wch;                        // [L][1024][3072] concat
    __half* wc_o   = wc_qkv + Lq * 3 * DD;
    __half* wc_1   = wc_o   + Lq * DD;           // W1 [D, FF]
    __half* wc_2   = wc_1   + Lq * DF;           // W2 [FF, D]

    const int n8dd  = (int)(Lq * DD / 8);
    const int gsall = n8dd / (256 * 4);
    const int n8df  = (int)(Lq * DF / 8);
    const int gf    = n8df / (256 * 4);
    const int n8l0  = (int)(DD / 8);
    const int g0    = n8l0 / (256 * 4);
    const int n8r   = n8dd - n8l0;
    const int gr    = n8r / (256 * 4);
    const size_t SRCL = DD / 4;
    const size_t DSTL = (size_t)1024 * 384;

    // ---- forked prologue
    cudaEventRecord(ev0, 0);
    cudaStreamWaitEvent(side, ev0, 0);

    embed_pe<<<(Mq * Dq) / 256, 256, 0, side>>>(src, emb, xh);
    bias_cat<<<(Lq * QKVN) / 256, 256, 0, side>>>(bqp, bkp, bvp, bqkv);
    cudaEventRecord(evA, side);
    wconv <<<gsall, 256, 0, side>>>((const float4*)Wop, (uint4*)wc_o, n8dd);
    wconvs<<<gr, 256, 0, side>>>((const float4*)Wqp + SRCL,
                                 (uint4*)wc_qkv + DSTL,       n8r);
    wconvs<<<gr, 256, 0, side>>>((const float4*)Wkp + SRCL,
                                 (uint4*)wc_qkv + DSTL + 128, n8r);
    wconvs<<<gr, 256, 0, side>>>((const float4*)Wvp + SRCL,
                                 (uint4*)wc_qkv + DSTL + 256, n8r);
    wconv <<<gf, 256, 0, side>>>((const float4*)W1p, (uint4*)wc_1, n8df);
    wconv <<<gf, 256, 0, side>>>((const float4*)W2p, (uint4*)wc_2, n8df);
    cudaEventRecord(evB, side);

    wconvs<<<g0, 256>>>((const float4*)Wqp, (uint4*)wc_qkv,       n8l0);
    wconvs<<<g0, 256>>>((const float4*)Wkp, (uint4*)wc_qkv + 128, n8l0);
    wconvs<<<g0, 256>>>((const float4*)Wvp, (uint4*)wc_qkv + 256, n8l0);
    cudaStreamWaitEvent(0, evA, 0);

    for (int l = 0; l < Lq; l++) {
        gemm(xh, Dq, wc_qkv + (size_t)l * 1024 * QKVN, QKVN,
             qkvh, QKVN, Mq, QKVN, Dq, bqkv + l * QKVN, 0);

        {
            dim3 grid(Sq / 128, Bq * Hq);
            flash_attn<<<grid, 256, FA_SMEM>>>(qkvh, qkvh + 1024, qkvh + 2048,
                                               mask, ctxh, QKVN);
        }

        if (l == 0)
            cudaStreamWaitEvent(0, evB, 0);

        gemm(ctxh, Dq, wc_o + l * DD, Dq, t1h, Dq, Mq, Dq, Dq, bop + l * Dq, 0);
        add_ln<<<Mq, 256>>>(t1h, xh, l1s + l * Dq, l1b + l * Dq, xh, nullptr);

        gemm(xh, Dq, wc_1 + l * DF, FFq, ffh, FFq, Mq, FFq, Dq, b1p + l * FFq, 1);
        gemm(ffh, FFq, wc_2 + l * DF, Dq, t1h, Dq, Mq, Dq, FFq, b2p + l * Dq, 0);
        add_ln<<<Mq, 256>>>(t1h, xh, l2s + l * Dq, l2b + l * Dq,
                            (l == Lq - 1) ? nullptr : xh,
                            (l == Lq - 1) ? out : nullptr);
    }
}